// round 1
// baseline (speedup 1.0000x reference)
#include <cuda_runtime.h>
#include <cuda_bf16.h>
#include <math.h>

// Problem constants
#define PB 256      // batch
#define PL 64       // leaves
#define PD 1024     // dim
#define PC 500      // classes
#define PN 127      // nodes = 2L-1
#define PS 63       // steps = L-1

// Scratch: time-domain node vectors and full complex spectra.
static __device__ float  g_td[(size_t)PB * PN * PD];        // 133 MB
static __device__ float2 g_fd[(size_t)PB * PN * PD];        // 266 MB

// ---------------------------------------------------------------------------
// Block-wide sum reduction (256 threads), result broadcast to all threads.
__device__ __forceinline__ float blockReduceAll(float v, float* red, int tid) {
#pragma unroll
    for (int o = 16; o > 0; o >>= 1) v += __shfl_xor_sync(0xffffffffu, v, o);
    if ((tid & 31) == 0) red[tid >> 5] = v;
    __syncthreads();
    if (tid == 0) {
        float t = 0.f;
#pragma unroll
        for (int i = 0; i < 8; i++) t += red[i];
        red[0] = t;
    }
    __syncthreads();
    float t = red[0];
    __syncthreads();
    return t;
}

// ---------------------------------------------------------------------------
// In-place radix-2 1024-point complex FFT in shared memory. 256 threads.
// forward: e^{-2pi i kn/N}; inverse: e^{+...} (caller applies 1/N scale).
__device__ __forceinline__ void fft1024_sh(float2* s, int tid, bool inverse) {
    // bit-reversal permutation (10 bits)
#pragma unroll
    for (int q = 0; q < 4; q++) {
        int i = tid + q * 256;
        int j = __brev((unsigned)i) >> 22;
        if (i < j) { float2 t = s[i]; s[i] = s[j]; s[j] = t; }
    }
    __syncthreads();
    const float sgn = inverse ? 1.f : -1.f;
    for (int len = 2; len <= 1024; len <<= 1) {
        int half = len >> 1;
        float base = sgn * 6.283185307179586f / (float)len;
#pragma unroll
        for (int q = 0; q < 2; q++) {
            int t = tid + q * 256;           // 512 butterflies per stage
            int pos = t & (half - 1);
            int i = 2 * t - pos;             // = (t/half)*len + pos
            int j = i + half;
            float sn, cs;
            __sincosf(base * (float)pos, &sn, &cs);
            float2 u = s[i], v = s[j];
            float tr = v.x * cs - v.y * sn;
            float ti = v.x * sn + v.y * cs;
            s[i] = make_float2(u.x + tr, u.y + ti);
            s[j] = make_float2(u.x - tr, u.y - ti);
        }
        __syncthreads();
    }
}

// ---------------------------------------------------------------------------
// Kernel 1: leaf gather + mask + L2-normalize -> TD; forward FFT -> FD.
// grid = B*L blocks, 256 threads.
__global__ void leaf_kernel(const int* __restrict__ ids,
                            const int* __restrict__ mask,
                            const float* __restrict__ emb) {
    __shared__ float2 s[1024];
    __shared__ float red[8];
    int blk = blockIdx.x;                 // b*L + l
    int tid = threadIdx.x;
    int id = ids[blk];
    int mk = mask[blk];
    const float* row = emb + (size_t)id * PD;

    float v[4];
    float ss = 0.f;
#pragma unroll
    for (int q = 0; q < 4; q++) {
        int d = tid + q * 256;
        float x = (mk > 0) ? row[d] : 0.f;
        v[q] = x;
        ss += x * x;
    }
    ss = blockReduceAll(ss, red, tid);
    float inv = 1.f / (sqrtf(ss) + 1e-6f);

    int b = blk >> 6, l = blk & 63;
    size_t node = (size_t)b * PN + l;
    float* td = g_td + node * PD;
#pragma unroll
    for (int q = 0; q < 4; q++) {
        int d = tid + q * 256;
        float x = v[q] * inv;
        td[d] = x;
        s[d] = make_float2(x, 0.f);
    }
    __syncthreads();
    fft1024_sh(s, tid, false);
    float2* fd = g_fd + node * PD;
#pragma unroll
    for (int q = 0; q < 4; q++) {
        int d = tid + q * 256;
        fd[d] = s[d];
    }
}

// ---------------------------------------------------------------------------
// Kernel 2: per-batch sequential composition entirely in frequency domain.
//   C[k] = conj(Fl[k]) * Fr[k];   ||c_time|| = sqrt(sum|C|^2 / D)  (Parseval)
//   F_node = C / (||c_time|| + 1e-6)
// Last-written node cached in SMEM to break the HBM round-trip in the chain.
// grid = B blocks, 256 threads.
__global__ void compose_kernel(const int* __restrict__ info) {
    __shared__ float2 sh[1024];
    __shared__ float red[8];
    int b = blockIdx.x, tid = threadIdx.x;
    const int* bi = info + (size_t)b * PS * 3;
    float2* fdb = g_fd + (size_t)b * PN * PD;
    int last = -1;
    for (int st = 0; st < PS; st++) {
        int i0 = bi[st * 3 + 0];
        int i1 = bi[st * 3 + 1];
        int i2 = bi[st * 3 + 2];
        float ss = 0.f;
        float2 cr[4];
#pragma unroll
        for (int q = 0; q < 4; q++) {
            int k = tid + q * 256;
            float2 fl = (i0 == last) ? sh[k] : fdb[(size_t)i0 * PD + k];
            float2 fr = (i1 == last) ? sh[k] : fdb[(size_t)i1 * PD + k];
            float cx = fl.x * fr.x + fl.y * fr.y;   // conj(fl)*fr
            float cy = fl.x * fr.y - fl.y * fr.x;
            cr[q] = make_float2(cx, cy);
            ss += cx * cx + cy * cy;
        }
        ss = blockReduceAll(ss, red, tid);          // includes syncs
        float inv = 1.f / (sqrtf(ss * (1.f / (float)PD)) + 1e-6f);
#pragma unroll
        for (int q = 0; q < 4; q++) {
            int k = tid + q * 256;
            float2 c = make_float2(cr[q].x * inv, cr[q].y * inv);
            sh[k] = c;
            fdb[(size_t)i2 * PD + k] = c;
        }
        last = i2;
        __syncthreads();
    }
}

// ---------------------------------------------------------------------------
// Kernel 3: inverse FFT of internal nodes -> TD (real part, scaled 1/D).
// grid = B*S blocks, 256 threads.
__global__ void irfft_kernel() {
    __shared__ float2 s[1024];
    int blk = blockIdx.x;                 // b*S + t
    int b = blk / PS, t = blk - b * PS;
    size_t node = (size_t)b * PN + PL + t;
    const float2* fd = g_fd + node * PD;
    int tid = threadIdx.x;
#pragma unroll
    for (int q = 0; q < 4; q++) {
        int k = tid + q * 256;
        s[k] = fd[k];
    }
    __syncthreads();
    fft1024_sh(s, tid, true);
    float* td = g_td + node * PD;
    const float sc = 1.f / (float)PD;
#pragma unroll
    for (int q = 0; q < 4; q++) {
        int k = tid + q * 256;
        td[k] = s[k].x * sc;
    }
}

// ---------------------------------------------------------------------------
// Kernel 4: out = sigmoid(TD(32512x1024) @ W^T(1024x500) + b)
// 128x128x16 tiles, 256 threads, 8x8 register micro-tiles.
#define BK 16
#define LDS_STRIDE 132   // 128 + 4 pad (bank-conflict-free transposed stores)

__global__ __launch_bounds__(256, 2)
void gemm_kernel(const float* __restrict__ W,
                 const float* __restrict__ bias,
                 float* __restrict__ out) {
    __shared__ float As[BK * LDS_STRIDE];
    __shared__ float Bs[BK * LDS_STRIDE];
    const int m0 = blockIdx.y * 128;
    const int c0 = blockIdx.x * 128;
    const int tid = threadIdx.x;
    const int tx = tid & 15, ty = tid >> 4;
    const float* A = g_td;

    float acc[8][8];
#pragma unroll
    for (int i = 0; i < 8; i++)
#pragma unroll
        for (int j = 0; j < 8; j++) acc[i][j] = 0.f;

    for (int kk = 0; kk < PD; kk += BK) {
        __syncthreads();
#pragma unroll
        for (int h = 0; h < 2; h++) {
            int idx = tid + h * 256;          // 512 float4 loads per operand
            int row = idx >> 2, kq = idx & 3;
            float4 av = *(const float4*)(A + (size_t)(m0 + row) * PD + kk + kq * 4);
            As[(kq * 4 + 0) * LDS_STRIDE + row] = av.x;
            As[(kq * 4 + 1) * LDS_STRIDE + row] = av.y;
            As[(kq * 4 + 2) * LDS_STRIDE + row] = av.z;
            As[(kq * 4 + 3) * LDS_STRIDE + row] = av.w;
            int c = c0 + row;
            float4 bv = make_float4(0.f, 0.f, 0.f, 0.f);
            if (c < PC) bv = *(const float4*)(W + (size_t)c * PD + kk + kq * 4);
            Bs[(kq * 4 + 0) * LDS_STRIDE + row] = bv.x;
            Bs[(kq * 4 + 1) * LDS_STRIDE + row] = bv.y;
            Bs[(kq * 4 + 2) * LDS_STRIDE + row] = bv.z;
            Bs[(kq * 4 + 3) * LDS_STRIDE + row] = bv.w;
        }
        __syncthreads();
#pragma unroll
        for (int k = 0; k < BK; k++) {
            float4 a0 = *(const float4*)&As[k * LDS_STRIDE + ty * 8];
            float4 a1 = *(const float4*)&As[k * LDS_STRIDE + ty * 8 + 4];
            float4 b0 = *(const float4*)&Bs[k * LDS_STRIDE + tx * 8];
            float4 b1 = *(const float4*)&Bs[k * LDS_STRIDE + tx * 8 + 4];
            float a[8] = {a0.x, a0.y, a0.z, a0.w, a1.x, a1.y, a1.z, a1.w};
            float bb[8] = {b0.x, b0.y, b0.z, b0.w, b1.x, b1.y, b1.z, b1.w};
#pragma unroll
            for (int i = 0; i < 8; i++)
#pragma unroll
                for (int j = 0; j < 8; j++)
                    acc[i][j] = fmaf(a[i], bb[j], acc[i][j]);
        }
    }

#pragma unroll
    for (int i = 0; i < 8; i++) {
        int m = m0 + ty * 8 + i;
#pragma unroll
        for (int j = 0; j < 8; j++) {
            int c = c0 + tx * 8 + j;
            if (c < PC) {
                float x = acc[i][j] + bias[c];
                out[(size_t)m * PC + c] = 1.f / (1.f + __expf(-x));
            }
        }
    }
}

// ---------------------------------------------------------------------------
extern "C" void kernel_launch(void* const* d_in, const int* in_sizes, int n_in,
                              void* d_out, int out_size) {
    const int*   ids  = (const int*)d_in[0];    // leaf_content_id  (B, L)
    const int*   mask = (const int*)d_in[1];    // content_mask     (B, L)
    const int*   info = (const int*)d_in[2];    // composition_info (B, S, 3)
    const float* emb  = (const float*)d_in[3];  // emb_weight       (V, D)
    const float* W    = (const float*)d_in[4];  // lin_w            (C, D)
    const float* bias = (const float*)d_in[5];  // lin_b            (C,)
    float* out = (float*)d_out;                 // (B, N, C) fp32

    leaf_kernel<<<PB * PL, 256>>>(ids, mask, emb);
    compose_kernel<<<PB, 256>>>(info);
    irfft_kernel<<<PB * PS, 256>>>();
    dim3 gg((PC + 127) / 128, (PB * PN) / 128); // 4 x 254
    gemm_kernel<<<gg, 256>>>(W, bias, out);
}

// round 3
// speedup vs baseline: 1.3328x; 1.3328x over previous
#include <cuda_runtime.h>
#include <cuda_bf16.h>
#include <mma.h>
#include <math.h>
#include <cstdint>

using namespace nvcuda;

// Problem constants
#define PB 256      // batch
#define PL 64       // leaves
#define PD 1024     // dim
#define PC 500      // classes
#define PN 127      // nodes = 2L-1
#define PS 63       // steps = L-1

// Scratch: time-domain node vectors and full complex spectra.
static __device__ float  g_td[(size_t)PB * PN * PD];        // 133 MB
static __device__ float2 g_fd[(size_t)PB * PN * PD];        // 266 MB

// ---------------------------------------------------------------------------
// Block-wide sum reduction (256 threads), result broadcast to all threads.
__device__ __forceinline__ float blockReduceAll(float v, float* red, int tid) {
#pragma unroll
    for (int o = 16; o > 0; o >>= 1) v += __shfl_xor_sync(0xffffffffu, v, o);
    if ((tid & 31) == 0) red[tid >> 5] = v;
    __syncthreads();
    if (tid == 0) {
        float t = 0.f;
#pragma unroll
        for (int i = 0; i < 8; i++) t += red[i];
        red[0] = t;
    }
    __syncthreads();
    float t = red[0];
    __syncthreads();
    return t;
}

// ---------------------------------------------------------------------------
// In-place radix-2 1024-point complex FFT in shared memory. 256 threads.
__device__ __forceinline__ void fft1024_sh(float2* s, int tid, bool inverse) {
#pragma unroll
    for (int q = 0; q < 4; q++) {
        int i = tid + q * 256;
        int j = __brev((unsigned)i) >> 22;
        if (i < j) { float2 t = s[i]; s[i] = s[j]; s[j] = t; }
    }
    __syncthreads();
    const float sgn = inverse ? 1.f : -1.f;
    for (int len = 2; len <= 1024; len <<= 1) {
        int half = len >> 1;
        float base = sgn * 6.283185307179586f / (float)len;
#pragma unroll
        for (int q = 0; q < 2; q++) {
            int t = tid + q * 256;
            int pos = t & (half - 1);
            int i = 2 * t - pos;
            int j = i + half;
            float sn, cs;
            __sincosf(base * (float)pos, &sn, &cs);
            float2 u = s[i], v = s[j];
            float tr = v.x * cs - v.y * sn;
            float ti = v.x * sn + v.y * cs;
            s[i] = make_float2(u.x + tr, u.y + ti);
            s[j] = make_float2(u.x - tr, u.y - ti);
        }
        __syncthreads();
    }
}

// ---------------------------------------------------------------------------
// Kernel 1: leaf gather + mask + L2-normalize -> TD; forward FFT -> FD.
__global__ void leaf_kernel(const int* __restrict__ ids,
                            const int* __restrict__ mask,
                            const float* __restrict__ emb) {
    __shared__ float2 s[1024];
    __shared__ float red[8];
    int blk = blockIdx.x;
    int tid = threadIdx.x;
    int id = ids[blk];
    int mk = mask[blk];
    const float* row = emb + (size_t)id * PD;

    float v[4];
    float ss = 0.f;
#pragma unroll
    for (int q = 0; q < 4; q++) {
        int d = tid + q * 256;
        float x = (mk > 0) ? row[d] : 0.f;
        v[q] = x;
        ss += x * x;
    }
    ss = blockReduceAll(ss, red, tid);
    float inv = 1.f / (sqrtf(ss) + 1e-6f);

    int b = blk >> 6, l = blk & 63;
    size_t node = (size_t)b * PN + l;
    float* td = g_td + node * PD;
#pragma unroll
    for (int q = 0; q < 4; q++) {
        int d = tid + q * 256;
        float x = v[q] * inv;
        td[d] = x;
        s[d] = make_float2(x, 0.f);
    }
    __syncthreads();
    fft1024_sh(s, tid, false);
    float2* fd = g_fd + node * PD;
#pragma unroll
    for (int q = 0; q < 4; q++) {
        int d = tid + q * 256;
        fd[d] = s[d];
    }
}

// ---------------------------------------------------------------------------
// Kernel 2: per-batch sequential composition in frequency domain, with
// register prefetch of the next step's operands to hide load latency behind
// the block reduction. Each thread's sh[] slots are thread-private.
__global__ void compose_kernel(const int* __restrict__ info) {
    __shared__ float2 sh[1024];
    __shared__ float red[8];
    int b = blockIdx.x, tid = threadIdx.x;
    const int* bi = info + (size_t)b * PS * 3;
    float2* fdb = g_fd + (size_t)b * PN * PD;

    int i0 = bi[0], i1 = bi[1], i2 = bi[2];
    float2 pl[4], pr[4];
#pragma unroll
    for (int q = 0; q < 4; q++) {
        int k = tid + q * 256;
        pl[q] = fdb[(size_t)i0 * PD + k];
        pr[q] = fdb[(size_t)i1 * PD + k];
    }
    int last = -1;
    for (int st = 0; st < PS; st++) {
        float ss = 0.f;
        float2 cr[4];
#pragma unroll
        for (int q = 0; q < 4; q++) {
            int k = tid + q * 256;
            float2 fl = (i0 == last) ? sh[k] : pl[q];
            float2 fr = (i1 == last) ? sh[k] : pr[q];
            float cx = fl.x * fr.x + fl.y * fr.y;   // conj(fl)*fr
            float cy = fl.x * fr.y - fl.y * fr.x;
            cr[q] = make_float2(cx, cy);
            ss += cx * cx + cy * cy;
        }
        // Prefetch next step's operands (skip any that will come from sh).
        int n0 = i0, n1 = i1, n2 = i2;
        if (st + 1 < PS) {
            n0 = bi[(st + 1) * 3 + 0];
            n1 = bi[(st + 1) * 3 + 1];
            n2 = bi[(st + 1) * 3 + 2];
#pragma unroll
            for (int q = 0; q < 4; q++) {
                int k = tid + q * 256;
                if (n0 != i2) pl[q] = fdb[(size_t)n0 * PD + k];
                if (n1 != i2) pr[q] = fdb[(size_t)n1 * PD + k];
            }
        }
        ss = blockReduceAll(ss, red, tid);
        float inv = 1.f / (sqrtf(ss * (1.f / (float)PD)) + 1e-6f);
#pragma unroll
        for (int q = 0; q < 4; q++) {
            int k = tid + q * 256;
            float2 c = make_float2(cr[q].x * inv, cr[q].y * inv);
            sh[k] = c;
            fdb[(size_t)i2 * PD + k] = c;
        }
        last = i2; i0 = n0; i1 = n1; i2 = n2;
    }
}

// ---------------------------------------------------------------------------
// Kernel 3: inverse FFT of internal nodes -> TD.
__global__ void irfft_kernel() {
    __shared__ float2 s[1024];
    int blk = blockIdx.x;
    int b = blk / PS, t = blk - b * PS;
    size_t node = (size_t)b * PN + PL + t;
    const float2* fd = g_fd + node * PD;
    int tid = threadIdx.x;
#pragma unroll
    for (int q = 0; q < 4; q++) {
        int k = tid + q * 256;
        s[k] = fd[k];
    }
    __syncthreads();
    fft1024_sh(s, tid, true);
    float* td = g_td + node * PD;
    const float sc = 1.f / (float)PD;
#pragma unroll
    for (int q = 0; q < 4; q++) {
        int k = tid + q * 256;
        td[k] = s[k].x * sc;
    }
}

// ===========================================================================
// wmma tf32 GEMM: out = sigmoid(TD(32512x1024) @ W^T(1024x500) + b)
// 128x128 block tile, 8 warps (4x2), 32x64 warp tiles, BK=16,
// cp.async double-buffered smem. HMMA truncates operands to tf32 (safe:
// resulting relative logit bias ~5e-4 << harness threshold on sigmoid out).
// ===========================================================================
#define BKG 16
#define LDK 24   // 16 + 8 pad; row = 96B (16B-aligned for cp.async), ldm%4==0

#define CP_ASYNC16(dst, src) \
    asm volatile("cp.async.ca.shared.global [%0], [%1], 16;\n" :: "r"(dst), "l"(src))
#define CP_COMMIT() asm volatile("cp.async.commit_group;\n" ::: "memory")
#define CP_WAIT(n)  asm volatile("cp.async.wait_group %0;\n" :: "n"(n) : "memory")

__device__ __forceinline__ uint32_t smem_u32(const void* p) {
    uint32_t a;
    asm("{ .reg .u64 t; cvta.to.shared.u64 t, %1; cvt.u32.u64 %0, t; }" : "=r"(a) : "l"(p));
    return a;
}

__global__ __launch_bounds__(256, 2)
void gemm_wmma_kernel(const float* __restrict__ W,
                      const float* __restrict__ bias,
                      float* __restrict__ out) {
    __shared__ float As[2][128 * LDK];
    __shared__ float Bs[2][128 * LDK];

    const int tid = threadIdx.x;
    const int wid = tid >> 5;
    const int lid = tid & 31;
    const int wr = wid & 3;          // warp row (0..3) -> 32 rows each
    const int wc = wid >> 2;         // warp col (0..1) -> 64 cols each
    const int m0 = blockIdx.y * 128;
    const int c0 = blockIdx.x * 128;
    const float* A = g_td;

    // Zero B rows beyond PC (never written by cp.async).
    if (c0 + 128 > PC) {
        for (int idx = tid; idx < 128 * LDK; idx += 256) {
            int row = idx / LDK;
            if (c0 + row >= PC) { Bs[0][idx] = 0.f; Bs[1][idx] = 0.f; }
        }
    }
    __syncthreads();

    const uint32_t sA0 = smem_u32(&As[0][0]);
    const uint32_t sA1 = smem_u32(&As[1][0]);
    const uint32_t sB0 = smem_u32(&Bs[0][0]);
    const uint32_t sB1 = smem_u32(&Bs[1][0]);

    // Stage loader: A tile 128x16, B tile 128x16 (512 float4 each).
    auto load_stage = [&](int stage, int kk) {
        uint32_t sA = stage ? sA1 : sA0;
        uint32_t sB = stage ? sB1 : sB0;
#pragma unroll
        for (int i = 0; i < 2; i++) {
            int idx = tid + i * 256;
            int row = idx >> 2, q = idx & 3;
            CP_ASYNC16(sA + (uint32_t)(row * LDK + q * 4) * 4,
                       A + (size_t)(m0 + row) * PD + kk + q * 4);
        }
#pragma unroll
        for (int i = 0; i < 2; i++) {
            int idx = tid + i * 256;
            int row = idx >> 2, q = idx & 3;
            if (c0 + row < PC)
                CP_ASYNC16(sB + (uint32_t)(row * LDK + q * 4) * 4,
                           W + (size_t)(c0 + row) * PD + kk + q * 4);
        }
    };

    wmma::fragment<wmma::accumulator, 16, 16, 8, float> acc[2][4];
#pragma unroll
    for (int i = 0; i < 2; i++)
#pragma unroll
        for (int j = 0; j < 4; j++) wmma::fill_fragment(acc[i][j], 0.f);

    load_stage(0, 0);
    CP_COMMIT();

    const int NK = PD / BKG;   // 64
    for (int kt = 0; kt < NK; kt++) {
        const int cur = kt & 1;
        if (kt + 1 < NK) {
            load_stage(cur ^ 1, (kt + 1) * BKG);
            CP_COMMIT();
            CP_WAIT(1);
        } else {
            CP_WAIT(0);
        }
        __syncthreads();

#pragma unroll
        for (int ks = 0; ks < 2; ks++) {
            wmma::fragment<wmma::matrix_a, 16, 16, 8, wmma::precision::tf32, wmma::row_major> af[2];
            wmma::fragment<wmma::matrix_b, 16, 16, 8, wmma::precision::tf32, wmma::col_major> bf[4];
#pragma unroll
            for (int i = 0; i < 2; i++)
                wmma::load_matrix_sync(af[i], &As[cur][(wr * 32 + i * 16) * LDK + ks * 8], LDK);
#pragma unroll
            for (int j = 0; j < 4; j++)
                wmma::load_matrix_sync(bf[j], &Bs[cur][(wc * 64 + j * 16) * LDK + ks * 8], LDK);
#pragma unroll
            for (int i = 0; i < 2; i++)
#pragma unroll
                for (int j = 0; j < 4; j++)
                    wmma::mma_sync(acc[i][j], af[i], bf[j], acc[i][j]);
        }
        __syncthreads();
    }

    // Epilogue: stage each 16x16 fragment through smem (reuse As[0]),
    // apply bias + sigmoid, write out.
    float* stage = &As[0][0] + wid * 256;
#pragma unroll
    for (int i = 0; i < 2; i++) {
#pragma unroll
        for (int j = 0; j < 4; j++) {
            wmma::store_matrix_sync(stage, acc[i][j], 16, wmma::mem_row_major);
            __syncwarp();
#pragma unroll
            for (int e = 0; e < 8; e++) {
                int elem = lid * 8 + e;
                int r = elem >> 4, cc = elem & 15;
                int m = m0 + wr * 32 + i * 16 + r;
                int c = c0 + wc * 64 + j * 16 + cc;
                if (c < PC) {
                    float x = stage[elem] + __ldg(bias + c);
                    out[(size_t)m * PC + c] = 1.f / (1.f + __expf(-x));
                }
            }
            __syncwarp();
        }
    }
}

// ---------------------------------------------------------------------------
extern "C" void kernel_launch(void* const* d_in, const int* in_sizes, int n_in,
                              void* d_out, int out_size) {
    const int*   ids  = (const int*)d_in[0];
    const int*   mask = (const int*)d_in[1];
    const int*   info = (const int*)d_in[2];
    const float* emb  = (const float*)d_in[3];
    const float* W    = (const float*)d_in[4];
    const float* bias = (const float*)d_in[5];
    float* out = (float*)d_out;

    leaf_kernel<<<PB * PL, 256>>>(ids, mask, emb);
    compose_kernel<<<PB, 256>>>(info);
    irfft_kernel<<<PB * PS, 256>>>();
    dim3 gg((PC + 127) / 128, (PB * PN) / 128);   // 4 x 254
    gemm_wmma_kernel<<<gg, 256>>>(W, bias, out);
}

// round 4
// speedup vs baseline: 1.8572x; 1.3934x over previous
#include <cuda_runtime.h>
#include <cuda_bf16.h>
#include <mma.h>
#include <math.h>
#include <cstdint>

using namespace nvcuda;

// Problem constants
#define PB 256      // batch
#define PL 64       // leaves
#define PD 1024     // dim
#define PC 500      // classes
#define PN 127      // nodes = 2L-1
#define PS 63       // steps = L-1

// Scratch
static __device__ __nv_bfloat16 g_tdb[(size_t)PB * PN * PD];  // 66 MB (GEMM A)
static __device__ float2        g_fd[(size_t)PB * PN * PD];   // 266 MB (spectra)
static __device__ __nv_bfloat16 g_wb[(size_t)PC * PD];        // 1 MB  (W in bf16)
static __device__ float2        g_tw[1024];                   // twiddle table

// ---------------------------------------------------------------------------
__global__ void twiddle_kernel() {
    int i = threadIdx.x + blockIdx.x * blockDim.x;
    if (i >= 1024) return;
    if (i == 0) { g_tw[0] = make_float2(1.f, 0.f); return; }
    int half = 1 << (31 - __clz(i));
    int pos = i - half;
    float ang = -3.14159265358979323846f * (float)pos / (float)half; // -2*pi*pos/(2*half)
    float s, c;
    sincosf(ang, &s, &c);
    g_tw[i] = make_float2(c, s);
}

__global__ void wconv_kernel(const float* __restrict__ W) {
    int i = blockIdx.x * 1024 + threadIdx.x * 4;
    float4 v = *(const float4*)(W + i);
    __nv_bfloat16* o = g_wb + i;
    o[0] = __float2bfloat16(v.x);
    o[1] = __float2bfloat16(v.y);
    o[2] = __float2bfloat16(v.z);
    o[3] = __float2bfloat16(v.w);
}

// ---------------------------------------------------------------------------
// Block-wide sum reduction (256 threads), result broadcast to all threads.
__device__ __forceinline__ float blockReduceAll(float v, float* red, int tid) {
#pragma unroll
    for (int o = 16; o > 0; o >>= 1) v += __shfl_xor_sync(0xffffffffu, v, o);
    if ((tid & 31) == 0) red[tid >> 5] = v;
    __syncthreads();
    if (tid == 0) {
        float t = 0.f;
#pragma unroll
        for (int i = 0; i < 8; i++) t += red[i];
        red[0] = t;
    }
    __syncthreads();
    float t = red[0];
    __syncthreads();
    return t;
}

// 512-thread variant (16 warps).
__device__ __forceinline__ float blockReduceAll16(float v, float* red, int tid) {
#pragma unroll
    for (int o = 16; o > 0; o >>= 1) v += __shfl_xor_sync(0xffffffffu, v, o);
    if ((tid & 31) == 0) red[tid >> 5] = v;
    __syncthreads();
    if (tid == 0) {
        float t = 0.f;
#pragma unroll
        for (int i = 0; i < 16; i++) t += red[i];
        red[0] = t;
    }
    __syncthreads();
    float t = red[0];
    __syncthreads();
    return t;
}

// ---------------------------------------------------------------------------
// In-place radix-2 1024-pt complex FFT, smem, 256 threads, table twiddles.
__device__ __forceinline__ void fft1024_sh(float2* s, const float2* tw,
                                           int tid, bool inverse) {
#pragma unroll
    for (int q = 0; q < 4; q++) {
        int i = tid + q * 256;
        int j = __brev((unsigned)i) >> 22;
        if (i < j) { float2 t = s[i]; s[i] = s[j]; s[j] = t; }
    }
    __syncthreads();
    const float wsg = inverse ? -1.f : 1.f;
    for (int len = 2; len <= 1024; len <<= 1) {
        int half = len >> 1;
#pragma unroll
        for (int q = 0; q < 2; q++) {
            int t = tid + q * 256;
            int pos = t & (half - 1);
            int i = 2 * t - pos;
            int j = i + half;
            float2 w = tw[half + pos];
            float cs = w.x, sn = wsg * w.y;   // forward: e^{-i}, inverse: conj
            float2 u = s[i], v = s[j];
            float tr = v.x * cs - v.y * sn;
            float ti = v.x * sn + v.y * cs;
            s[i] = make_float2(u.x + tr, u.y + ti);
            s[j] = make_float2(u.x - tr, u.y - ti);
        }
        __syncthreads();
    }
}

// ---------------------------------------------------------------------------
// Kernel 1: leaf gather + mask + L2-normalize -> bf16 TD; forward FFT -> FD.
__global__ void leaf_kernel(const int* __restrict__ ids,
                            const int* __restrict__ mask,
                            const float* __restrict__ emb) {
    __shared__ float2 s[1024];
    __shared__ float2 s_tw[1024];
    __shared__ float red[8];
    int blk = blockIdx.x;
    int tid = threadIdx.x;
    int id = ids[blk];
    int mk = mask[blk];
    const float* row = emb + (size_t)id * PD;

#pragma unroll
    for (int q = 0; q < 4; q++) s_tw[tid + q * 256] = g_tw[tid + q * 256];

    float v[4];
    float ss = 0.f;
#pragma unroll
    for (int q = 0; q < 4; q++) {
        int d = tid + q * 256;
        float x = (mk > 0) ? row[d] : 0.f;
        v[q] = x;
        ss += x * x;
    }
    ss = blockReduceAll(ss, red, tid);
    float inv = 1.f / (sqrtf(ss) + 1e-6f);

    int b = blk >> 6, l = blk & 63;
    size_t node = (size_t)b * PN + l;
    __nv_bfloat16* td = g_tdb + node * PD;
#pragma unroll
    for (int q = 0; q < 4; q++) {
        int d = tid + q * 256;
        float x = v[q] * inv;
        td[d] = __float2bfloat16(x);
        s[d] = make_float2(x, 0.f);
    }
    __syncthreads();
    fft1024_sh(s, s_tw, tid, false);
    float2* fd = g_fd + node * PD;
#pragma unroll
    for (int q = 0; q < 4; q++) {
        int d = tid + q * 256;
        fd[d] = s[d];
    }
}

// ---------------------------------------------------------------------------
// Kernel 2: per-batch sequential composition in frequency domain. 512 thr.
__global__ void compose_kernel(const int* __restrict__ info) {
    __shared__ float2 sh[1024];
    __shared__ float red[16];
    int b = blockIdx.x, tid = threadIdx.x;
    const int* bi = info + (size_t)b * PS * 3;
    float2* fdb = g_fd + (size_t)b * PN * PD;

    int i0 = bi[0], i1 = bi[1], i2 = bi[2];
    float2 pl[2], pr[2];
#pragma unroll
    for (int q = 0; q < 2; q++) {
        int k = tid + q * 512;
        pl[q] = fdb[(size_t)i0 * PD + k];
        pr[q] = fdb[(size_t)i1 * PD + k];
    }
    int last = -1;
    for (int st = 0; st < PS; st++) {
        float ss = 0.f;
        float2 cr[2];
#pragma unroll
        for (int q = 0; q < 2; q++) {
            int k = tid + q * 512;
            float2 fl = (i0 == last) ? sh[k] : pl[q];
            float2 fr = (i1 == last) ? sh[k] : pr[q];
            float cx = fl.x * fr.x + fl.y * fr.y;   // conj(fl)*fr
            float cy = fl.x * fr.y - fl.y * fr.x;
            cr[q] = make_float2(cx, cy);
            ss += cx * cx + cy * cy;
        }
        int n0 = i0, n1 = i1, n2 = i2;
        if (st + 1 < PS) {
            n0 = bi[(st + 1) * 3 + 0];
            n1 = bi[(st + 1) * 3 + 1];
            n2 = bi[(st + 1) * 3 + 2];
#pragma unroll
            for (int q = 0; q < 2; q++) {
                int k = tid + q * 512;
                if (n0 != i2) pl[q] = fdb[(size_t)n0 * PD + k];
                if (n1 != i2) pr[q] = fdb[(size_t)n1 * PD + k];
            }
        }
        ss = blockReduceAll16(ss, red, tid);
        float inv = 1.f / (sqrtf(ss * (1.f / (float)PD)) + 1e-6f);
#pragma unroll
        for (int q = 0; q < 2; q++) {
            int k = tid + q * 512;
            float2 c = make_float2(cr[q].x * inv, cr[q].y * inv);
            sh[k] = c;
            fdb[(size_t)i2 * PD + k] = c;
        }
        last = i2; i0 = n0; i1 = n1; i2 = n2;
    }
}

// ---------------------------------------------------------------------------
// Kernel 3: inverse FFT of internal nodes -> bf16 TD.
__global__ void irfft_kernel() {
    __shared__ float2 s[1024];
    __shared__ float2 s_tw[1024];
    int blk = blockIdx.x;
    int b = blk / PS, t = blk - b * PS;
    size_t node = (size_t)b * PN + PL + t;
    const float2* fd = g_fd + node * PD;
    int tid = threadIdx.x;
#pragma unroll
    for (int q = 0; q < 4; q++) {
        int k = tid + q * 256;
        s[k] = fd[k];
        s_tw[k] = g_tw[k];
    }
    __syncthreads();
    fft1024_sh(s, s_tw, tid, true);
    __nv_bfloat16* td = g_tdb + node * PD;
    const float sc = 1.f / (float)PD;
#pragma unroll
    for (int q = 0; q < 4; q++) {
        int k = tid + q * 256;
        td[k] = __float2bfloat16(s[k].x * sc);
    }
}

// ===========================================================================
// bf16 wmma GEMM: out = sigmoid(TDb(32512x1024) @ Wb^T(1024x500) + b)
// 128x128 block tile, 8 warps (4x2), 32x64 warp tiles, BK=32,
// cp.async double-buffered smem (40KB -> 2 CTAs/SM).
// ===========================================================================
#define BKG 32
#define LDKB 40   // bf16 elements per row (80B, 16B-aligned, mult of 8)

#define CP_ASYNC16(dst, src) \
    asm volatile("cp.async.ca.shared.global [%0], [%1], 16;\n" :: "r"(dst), "l"(src))
#define CP_COMMIT() asm volatile("cp.async.commit_group;\n" ::: "memory")
#define CP_WAIT(n)  asm volatile("cp.async.wait_group %0;\n" :: "n"(n) : "memory")

__device__ __forceinline__ uint32_t smem_u32(const void* p) {
    uint32_t a;
    asm("{ .reg .u64 t; cvta.to.shared.u64 t, %1; cvt.u32.u64 %0, t; }" : "=r"(a) : "l"(p));
    return a;
}

__global__ __launch_bounds__(256, 2)
void gemm_wmma_kernel(const float* __restrict__ bias,
                      float* __restrict__ out) {
    __shared__ alignas(16) __nv_bfloat16 As[2][128 * LDKB];
    __shared__ alignas(16) __nv_bfloat16 Bs[2][128 * LDKB];

    const int tid = threadIdx.x;
    const int wid = tid >> 5;
    const int lid = tid & 31;
    const int wr = wid & 3;          // warp row (0..3) -> 32 rows each
    const int wc = wid >> 2;         // warp col (0..1) -> 64 cols each
    const int m0 = blockIdx.y * 128;
    const int c0 = blockIdx.x * 128;
    const __nv_bfloat16* A = g_tdb;

    // Zero B rows beyond PC once (cp.async never writes them).
    if (c0 + 128 > PC) {
        for (int idx = tid; idx < 128 * LDKB; idx += 256) {
            int row = idx / LDKB;
            if (c0 + row >= PC) {
                Bs[0][idx] = __float2bfloat16(0.f);
                Bs[1][idx] = __float2bfloat16(0.f);
            }
        }
    }
    __syncthreads();

    const uint32_t sA0 = smem_u32(&As[0][0]);
    const uint32_t sA1 = smem_u32(&As[1][0]);
    const uint32_t sB0 = smem_u32(&Bs[0][0]);
    const uint32_t sB1 = smem_u32(&Bs[1][0]);

    // Stage loader: A/B tiles 128x32 bf16 = 512 x 16B chunks each.
    auto load_stage = [&](int stage, int kk) {
        uint32_t sA = stage ? sA1 : sA0;
        uint32_t sB = stage ? sB1 : sB0;
#pragma unroll
        for (int i = 0; i < 2; i++) {
            int idx = tid + i * 256;
            int row = idx >> 2, q = idx & 3;        // 4 chunks of 8 bf16 per row
            CP_ASYNC16(sA + (uint32_t)(row * LDKB + q * 8) * 2,
                       A + (size_t)(m0 + row) * PD + kk + q * 8);
        }
#pragma unroll
        for (int i = 0; i < 2; i++) {
            int idx = tid + i * 256;
            int row = idx >> 2, q = idx & 3;
            if (c0 + row < PC)
                CP_ASYNC16(sB + (uint32_t)(row * LDKB + q * 8) * 2,
                           g_wb + (size_t)(c0 + row) * PD + kk + q * 8);
        }
    };

    wmma::fragment<wmma::accumulator, 16, 16, 16, float> acc[2][4];
#pragma unroll
    for (int i = 0; i < 2; i++)
#pragma unroll
        for (int j = 0; j < 4; j++) wmma::fill_fragment(acc[i][j], 0.f);

    load_stage(0, 0);
    CP_COMMIT();

    const int NK = PD / BKG;   // 32
    for (int kt = 0; kt < NK; kt++) {
        const int cur = kt & 1;
        if (kt + 1 < NK) {
            load_stage(cur ^ 1, (kt + 1) * BKG);
            CP_COMMIT();
            CP_WAIT(1);
        } else {
            CP_WAIT(0);
        }
        __syncthreads();

#pragma unroll
        for (int ks = 0; ks < 2; ks++) {
            wmma::fragment<wmma::matrix_a, 16, 16, 16, __nv_bfloat16, wmma::row_major> af[2];
            wmma::fragment<wmma::matrix_b, 16, 16, 16, __nv_bfloat16, wmma::col_major> bf[4];
#pragma unroll
            for (int i = 0; i < 2; i++)
                wmma::load_matrix_sync(af[i], &As[cur][(wr * 32 + i * 16) * LDKB + ks * 16], LDKB);
#pragma unroll
            for (int j = 0; j < 4; j++)
                wmma::load_matrix_sync(bf[j], &Bs[cur][(wc * 64 + j * 16) * LDKB + ks * 16], LDKB);
#pragma unroll
            for (int i = 0; i < 2; i++)
#pragma unroll
                for (int j = 0; j < 4; j++)
                    wmma::mma_sync(acc[i][j], af[i], bf[j], acc[i][j]);
        }
        __syncthreads();
    }

    // Epilogue: stage each 16x16 fragment through smem, bias + sigmoid.
    float* stage = (float*)&As[0][0] + wid * 256;
#pragma unroll
    for (int i = 0; i < 2; i++) {
#pragma unroll
        for (int j = 0; j < 4; j++) {
            wmma::store_matrix_sync(stage, acc[i][j], 16, wmma::mem_row_major);
            __syncwarp();
#pragma unroll
            for (int e = 0; e < 8; e++) {
                int elem = lid * 8 + e;
                int r = elem >> 4, cc = elem & 15;
                int m = m0 + wr * 32 + i * 16 + r;
                int c = c0 + wc * 64 + j * 16 + cc;
                if (c < PC) {
                    float x = stage[elem] + __ldg(bias + c);
                    out[(size_t)m * PC + c] = 1.f / (1.f + __expf(-x));
                }
            }
            __syncwarp();
        }
    }
}

// ---------------------------------------------------------------------------
extern "C" void kernel_launch(void* const* d_in, const int* in_sizes, int n_in,
                              void* d_out, int out_size) {
    const int*   ids  = (const int*)d_in[0];
    const int*   mask = (const int*)d_in[1];
    const int*   info = (const int*)d_in[2];
    const float* emb  = (const float*)d_in[3];
    const float* W    = (const float*)d_in[4];
    const float* bias = (const float*)d_in[5];
    float* out = (float*)d_out;

    twiddle_kernel<<<4, 256>>>();
    wconv_kernel<<<PC, 256>>>(W);
    leaf_kernel<<<PB * PL, 256>>>(ids, mask, emb);
    compose_kernel<<<PB, 512>>>(info);
    irfft_kernel<<<PB * PS, 256>>>();
    dim3 gg((PC + 127) / 128, (PB * PN) / 128);   // 4 x 254
    gemm_wmma_kernel<<<gg, 256>>>(bias, out);
}

// round 5
// speedup vs baseline: 2.7323x; 1.4712x over previous
#include <cuda_runtime.h>
#include <cuda_bf16.h>
#include <mma.h>
#include <math.h>
#include <cstdint>

using namespace nvcuda;

// Problem constants
#define PB 256      // batch
#define PL 64       // leaves
#define PD 1024     // dim
#define PC 500      // classes
#define PN 127      // nodes = 2L-1
#define PS 63       // steps = L-1
#define HB 512      // half-spectrum bins stored per node

// Scratch
static __device__ __nv_bfloat16 g_tdb[(size_t)PB * PN * PD];  // 66 MB (GEMM A)
static __device__ float2        g_fd[(size_t)PB * PN * HB];   // 133 MB (half spectra)
static __device__ __nv_bfloat16 g_wb[(size_t)PC * PD];        // 1 MB  (W in bf16)
static __device__ float2        g_tw[1024];                   // twiddles e^{-i pi pos/half} at [half+pos]

// ---------------------------------------------------------------------------
__global__ void twiddle_kernel() {
    int i = threadIdx.x + blockIdx.x * blockDim.x;
    if (i >= 1024) return;
    if (i == 0) { g_tw[0] = make_float2(1.f, 0.f); return; }
    int half = 1 << (31 - __clz(i));
    int pos = i - half;
    float ang = -3.14159265358979323846f * (float)pos / (float)half;
    float s, c;
    sincosf(ang, &s, &c);
    g_tw[i] = make_float2(c, s);
}

__global__ void wconv_kernel(const float* __restrict__ W) {
    int i = blockIdx.x * 1024 + threadIdx.x * 4;
    float4 v = *(const float4*)(W + i);
    __nv_bfloat16* o = g_wb + i;
    o[0] = __float2bfloat16(v.x);
    o[1] = __float2bfloat16(v.y);
    o[2] = __float2bfloat16(v.z);
    o[3] = __float2bfloat16(v.w);
}

// ---------------------------------------------------------------------------
__device__ __forceinline__ float blockReduceAll(float v, float* red, int tid, int nw) {
#pragma unroll
    for (int o = 16; o > 0; o >>= 1) v += __shfl_xor_sync(0xffffffffu, v, o);
    if ((tid & 31) == 0) red[tid >> 5] = v;
    __syncthreads();
    if (tid == 0) {
        float t = 0.f;
        for (int i = 0; i < nw; i++) t += red[i];
        red[0] = t;
    }
    __syncthreads();
    float t = red[0];
    __syncthreads();
    return t;
}

// ---------------------------------------------------------------------------
// In-place radix-2 512-pt complex FFT, smem, 256 threads, table twiddles.
__device__ __forceinline__ void fft512_sh(float2* s, const float2* tw,
                                          int tid, bool inverse) {
#pragma unroll
    for (int q = 0; q < 2; q++) {
        int i = tid + q * 256;
        int j = __brev((unsigned)i) >> 23;
        if (i < j) { float2 t = s[i]; s[i] = s[j]; s[j] = t; }
    }
    __syncthreads();
    const float wsg = inverse ? -1.f : 1.f;
    for (int len = 2; len <= 512; len <<= 1) {
        int half = len >> 1;
        int pos = tid & (half - 1);
        int i = 2 * tid - pos;
        int j = i + half;
        float2 w = tw[half + pos];
        float cs = w.x, sn = wsg * w.y;
        float2 u = s[i], v = s[j];
        float tr = v.x * cs - v.y * sn;
        float ti = v.x * sn + v.y * cs;
        s[i] = make_float2(u.x + tr, u.y + ti);
        s[j] = make_float2(u.x - tr, u.y - ti);
        __syncthreads();
    }
}

// ---------------------------------------------------------------------------
// Kernel 1: leaf gather + mask + L2-normalize -> bf16 TD; rfft -> half FD.
// 256 threads. Real FFT via 512-pt complex FFT on (x[2n], x[2n+1]) + untangle.
__global__ void leaf_kernel(const int* __restrict__ ids,
                            const int* __restrict__ mask,
                            const float* __restrict__ emb) {
    __shared__ float2 s[512];
    __shared__ float2 s_tw[1024];
    __shared__ float red[8];
    int blk = blockIdx.x;
    int tid = threadIdx.x;
    int id = ids[blk];
    int mk = mask[blk];
    const float* row = emb + (size_t)id * PD;

#pragma unroll
    for (int q = 0; q < 4; q++) s_tw[tid + q * 256] = g_tw[tid + q * 256];

    float v[4];
    float ss = 0.f;
#pragma unroll
    for (int q = 0; q < 4; q++) {
        int d = tid + q * 256;
        float x = (mk > 0) ? row[d] : 0.f;
        v[q] = x;
        ss += x * x;
    }
    ss = blockReduceAll(ss, red, tid, 8);
    float inv = 1.f / (sqrtf(ss) + 1e-6f);

    int b = blk >> 6, l = blk & 63;
    size_t node = (size_t)b * PN + l;
    __nv_bfloat16* td = g_tdb + node * PD;
    float* xs = (float*)s;   // packed z[n] = (x[2n], x[2n+1]) by reinterpret
#pragma unroll
    for (int q = 0; q < 4; q++) {
        int d = tid + q * 256;
        float x = v[q] * inv;
        td[d] = __float2bfloat16(x);
        xs[d] = x;
    }
    __syncthreads();
    fft512_sh(s, s_tw, tid, false);

    // Untangle Z -> X[0..511] (X[512] packed into bin 0 .y)
    float2* fd = g_fd + node * HB;
    int k = tid;
    if (k == 0) {
        float2 z0 = s[0];
        fd[0] = make_float2(z0.x + z0.y, z0.x - z0.y);    // (X0, X512) both real
        float2 z = s[256];
        fd[256] = make_float2(z.x, -z.y);                 // X[256] = conj(Z[256])
    } else {
        float2 zk = s[k], zk2 = s[512 - k];
        float ex = 0.5f * (zk.x + zk2.x), ey = 0.5f * (zk.y - zk2.y);
        float dx = zk.x - zk2.x, dy = zk.y + zk2.y;
        float ox = 0.5f * dy, oy = -0.5f * dx;            // O = d * (-i/2)
        float2 w = s_tw[512 + k];                         // e^{-2pi i k/1024}
        float wx = w.x * ox - w.y * oy;
        float wy = w.x * oy + w.y * ox;
        fd[k]       = make_float2(ex + wx, ey + wy);
        fd[512 - k] = make_float2(ex - wx, -(ey - wy));   // conj(E - W*O)
    }
}

// ---------------------------------------------------------------------------
// Kernel 2: per-batch sequential composition on 512 half-spectrum bins.
// 512 threads, 1 bin each. Bin 0 packs (DC, Nyquist), both real.
__global__ void compose_kernel(const int* __restrict__ info) {
    __shared__ float2 sh[HB];
    __shared__ float red[16];
    int b = blockIdx.x, tid = threadIdx.x;
    const int* bi = info + (size_t)b * PS * 3;
    float2* fdb = g_fd + (size_t)b * PN * HB;

    int i0 = bi[0], i1 = bi[1], i2 = bi[2];
    float2 pl = fdb[(size_t)i0 * HB + tid];
    float2 pr = fdb[(size_t)i1 * HB + tid];
    int last = -1;
    for (int st = 0; st < PS; st++) {
        float2 fl = (i0 == last) ? sh[tid] : pl;
        float2 fr = (i1 == last) ? sh[tid] : pr;
        float2 c;
        float ss;
        if (tid == 0) {
            c = make_float2(fl.x * fr.x, fl.y * fr.y);    // (C0, C512) real
            ss = c.x * c.x + c.y * c.y;
        } else {
            c = make_float2(fl.x * fr.x + fl.y * fr.y,    // conj(fl)*fr
                            fl.x * fr.y - fl.y * fr.x);
            ss = 2.f * (c.x * c.x + c.y * c.y);
        }
        int n0 = i0, n1 = i1, n2 = i2;
        if (st + 1 < PS) {
            n0 = bi[(st + 1) * 3 + 0];
            n1 = bi[(st + 1) * 3 + 1];
            n2 = bi[(st + 1) * 3 + 2];
            if (n0 != i2) pl = fdb[(size_t)n0 * HB + tid];
            if (n1 != i2) pr = fdb[(size_t)n1 * HB + tid];
        }
        ss = blockReduceAll(ss, red, tid, 16);
        float inv = 1.f / (sqrtf(ss * (1.f / (float)PD)) + 1e-6f);
        float2 cc = make_float2(c.x * inv, c.y * inv);
        sh[tid] = cc;
        fdb[(size_t)i2 * HB + tid] = cc;
        last = i2; i0 = n0; i1 = n1; i2 = n2;
    }
}

// ---------------------------------------------------------------------------
// Kernel 3: inverse rfft of internal nodes -> bf16 TD. 256 threads.
__global__ void irfft_kernel() {
    __shared__ float2 s[512];
    __shared__ float2 s_tw[1024];
    int blk = blockIdx.x;
    int b = blk / PS, t = blk - b * PS;
    size_t node = (size_t)b * PN + PL + t;
    const float2* fd = g_fd + node * HB;
    int tid = threadIdx.x;
#pragma unroll
    for (int q = 0; q < 4; q++) s_tw[tid + q * 256] = g_tw[tid + q * 256];
    __syncthreads();

    // Reconstruct Z[0..511] from half spectrum.
    int k = tid;
    if (k == 0) {
        float2 p = fd[0];                                  // (X0, X512)
        s[0] = make_float2(0.5f * (p.x + p.y), 0.5f * (p.x - p.y));
        float2 x256 = fd[256];
        s[256] = make_float2(x256.x, -x256.y);             // Z[256] = conj(X[256])
    } else {
        float2 Xk = fd[k], Xk2 = fd[512 - k];
        float ex = 0.5f * (Xk.x + Xk2.x), ey = 0.5f * (Xk.y - Xk2.y);
        float dx = Xk.x - Xk2.x, dy = Xk.y + Xk2.y;
        float2 w = s_tw[512 + k];                          // W^k; O = d*conj(W)/2
        float ox = 0.5f * (dx * w.x + dy * w.y);
        float oy = 0.5f * (dy * w.x - dx * w.y);
        s[k]       = make_float2(ex - oy, ey + ox);        // E + iO
        s[512 - k] = make_float2(ex + oy, ox - ey);        // conj(E) + i*conj(O)
    }
    __syncthreads();
    fft512_sh(s, s_tw, tid, true);

    __nv_bfloat16* td = g_tdb + node * PD;
    const float* xs = (const float*)s;                     // x[2n]=z.x, x[2n+1]=z.y
    const float sc = 1.f / 512.f;
#pragma unroll
    for (int q = 0; q < 4; q++) {
        int d = tid + q * 256;
        td[d] = __float2bfloat16(xs[d] * sc);
    }
}

// ===========================================================================
// bf16 wmma GEMM: out = sigmoid(TDb(32512x1024) @ Wb^T(1024x500) + b)
// 128x128 block tile, 8 warps (4x2), 32x64 warp tiles, BK=32,
// 3-stage cp.async ring in dynamic smem (60KB, 2 CTAs/SM).
// ===========================================================================
#define BKG 32
#define LDKB 40   // bf16 per row (80B, 16B-aligned, mult of 8)
#define STG_ELEMS (128 * LDKB)

#define CP_ASYNC16(dst, src) \
    asm volatile("cp.async.cg.shared.global [%0], [%1], 16;\n" :: "r"(dst), "l"(src))
#define CP_COMMIT() asm volatile("cp.async.commit_group;\n" ::: "memory")
#define CP_WAIT(n)  asm volatile("cp.async.wait_group %0;\n" :: "n"(n) : "memory")

__device__ __forceinline__ uint32_t smem_u32(const void* p) {
    uint32_t a;
    asm("{ .reg .u64 t; cvta.to.shared.u64 t, %1; cvt.u32.u64 %0, t; }" : "=r"(a) : "l"(p));
    return a;
}

__global__ __launch_bounds__(256, 2)
void gemm_wmma_kernel(const float* __restrict__ bias,
                      float* __restrict__ out) {
    extern __shared__ __align__(16) char dsm[];
    __nv_bfloat16* As = (__nv_bfloat16*)dsm;               // 3 stages
    __nv_bfloat16* Bs = As + 3 * STG_ELEMS;

    const int tid = threadIdx.x;
    const int wid = tid >> 5;
    const int lid = tid & 31;
    const int wr = wid & 3;
    const int wc = wid >> 2;
    const int m0 = blockIdx.y * 128;
    const int c0 = blockIdx.x * 128;
    const __nv_bfloat16* A = g_tdb;

    // Zero B rows beyond PC in all stages (cp.async never writes them).
    if (c0 + 128 > PC) {
        for (int st = 0; st < 3; st++)
            for (int idx = tid; idx < STG_ELEMS; idx += 256) {
                int row = idx / LDKB;
                if (c0 + row >= PC) Bs[st * STG_ELEMS + idx] = __float2bfloat16(0.f);
            }
    }
    __syncthreads();

    const uint32_t sAb = smem_u32(As);
    const uint32_t sBb = smem_u32(Bs);

    auto load_stage = [&](int stage, int kk) {
        uint32_t sA = sAb + (uint32_t)stage * STG_ELEMS * 2;
        uint32_t sB = sBb + (uint32_t)stage * STG_ELEMS * 2;
#pragma unroll
        for (int i = 0; i < 2; i++) {
            int idx = tid + i * 256;
            int row = idx >> 2, q = idx & 3;
            CP_ASYNC16(sA + (uint32_t)(row * LDKB + q * 8) * 2,
                       A + (size_t)(m0 + row) * PD + kk + q * 8);
        }
#pragma unroll
        for (int i = 0; i < 2; i++) {
            int idx = tid + i * 256;
            int row = idx >> 2, q = idx & 3;
            if (c0 + row < PC)
                CP_ASYNC16(sB + (uint32_t)(row * LDKB + q * 8) * 2,
                           g_wb + (size_t)(c0 + row) * PD + kk + q * 8);
        }
    };

    wmma::fragment<wmma::accumulator, 16, 16, 16, float> acc[2][4];
#pragma unroll
    for (int i = 0; i < 2; i++)
#pragma unroll
        for (int j = 0; j < 4; j++) wmma::fill_fragment(acc[i][j], 0.f);

    load_stage(0, 0);
    CP_COMMIT();
    load_stage(1, BKG);
    CP_COMMIT();

    const int NK = PD / BKG;   // 32
    for (int kt = 0; kt < NK; kt++) {
        if (kt + 1 < NK) { CP_WAIT(1); } else { CP_WAIT(0); }
        __syncthreads();
        if (kt + 2 < NK) {
            load_stage((kt + 2) % 3, (kt + 2) * BKG);
            CP_COMMIT();
        }
        const __nv_bfloat16* Ac = As + (kt % 3) * STG_ELEMS;
        const __nv_bfloat16* Bc = Bs + (kt % 3) * STG_ELEMS;
#pragma unroll
        for (int ks = 0; ks < 2; ks++) {
            wmma::fragment<wmma::matrix_a, 16, 16, 16, __nv_bfloat16, wmma::row_major> af[2];
            wmma::fragment<wmma::matrix_b, 16, 16, 16, __nv_bfloat16, wmma::col_major> bf[4];
#pragma unroll
            for (int i = 0; i < 2; i++)
                wmma::load_matrix_sync(af[i], Ac + (wr * 32 + i * 16) * LDKB + ks * 16, LDKB);
#pragma unroll
            for (int j = 0; j < 4; j++)
                wmma::load_matrix_sync(bf[j], Bc + (wc * 64 + j * 16) * LDKB + ks * 16, LDKB);
#pragma unroll
            for (int i = 0; i < 2; i++)
#pragma unroll
                for (int j = 0; j < 4; j++)
                    wmma::mma_sync(acc[i][j], af[i], bf[j], acc[i][j]);
        }
    }
    __syncthreads();

    // Epilogue: stage fragments through smem, bias + sigmoid.
    float* stage = (float*)dsm + wid * 256;
#pragma unroll
    for (int i = 0; i < 2; i++) {
#pragma unroll
        for (int j = 0; j < 4; j++) {
            wmma::store_matrix_sync(stage, acc[i][j], 16, wmma::mem_row_major);
            __syncwarp();
#pragma unroll
            for (int e = 0; e < 8; e++) {
                int elem = lid * 8 + e;
                int r = elem >> 4, cc = elem & 15;
                int m = m0 + wr * 32 + i * 16 + r;
                int c = c0 + wc * 64 + j * 16 + cc;
                if (c < PC) {
                    float x = stage[elem] + __ldg(bias + c);
                    out[(size_t)m * PC + c] = 1.f / (1.f + __expf(-x));
                }
            }
            __syncwarp();
        }
    }
}

#define GEMM_SMEM (6 * STG_ELEMS * 2)   // 61440 bytes

// ---------------------------------------------------------------------------
extern "C" void kernel_launch(void* const* d_in, const int* in_sizes, int n_in,
                              void* d_out, int out_size) {
    const int*   ids  = (const int*)d_in[0];
    const int*   mask = (const int*)d_in[1];
    const int*   info = (const int*)d_in[2];
    const float* emb  = (const float*)d_in[3];
    const float* W    = (const float*)d_in[4];
    const float* bias = (const float*)d_in[5];
    float* out = (float*)d_out;

    twiddle_kernel<<<4, 256>>>();
    wconv_kernel<<<PC, 256>>>(W);
    leaf_kernel<<<PB * PL, 256>>>(ids, mask, emb);
    compose_kernel<<<PB, 512>>>(info);
    irfft_kernel<<<PB * PS, 256>>>();

    cudaFuncSetAttribute(gemm_wmma_kernel,
                         cudaFuncAttributeMaxDynamicSharedMemorySize, GEMM_SMEM);
    dim3 gg((PC + 127) / 128, (PB * PN) / 128);   // 4 x 254
    gemm_wmma_kernel<<<gg, 256, GEMM_SMEM>>>(bias, out);
}